// round 2
// baseline (speedup 1.0000x reference)
#include <cuda_runtime.h>
#include <math.h>

#define Bn 4
#define Ln 128
#define Hn 256
#define Cn 6
#define EMBD 400
#define BL 512
#define KC1 524
#define KFULL 1042
#define LSTM_BLOCKS 128

// ---------------- scratch layout (floats) ----------------
#define O_EMB   0
#define O_PRE   (O_EMB + 204800)          // 2*512*1024
#define O_H     (O_PRE + 1048576)         // 2*2*4*256 = 4096
#define O_CTX   (O_H + 4096)              // 512*512
#define O_Q     (O_CTX + 262144)
#define O_K     (O_Q + 262144)
#define O_CTX2  (O_K + 262144)
#define O_F     (O_CTX2 + 262144)         // 512*6
#define O_G     (O_F + 3072)
#define O_LM    (O_G + 3072)
#define O_F2    (O_LM + 3072)
#define O_G2    (O_F2 + 3072)
#define O_U     (O_G2 + 3072)             // 512*1024
#define O_V     (O_U + 524288)
#define O_U2    (O_V + 524288)
#define O_V2    (O_U2 + 524288)
#define O_ABU   (O_V2 + 524288)           // 512*524
#define O_ABV   (O_ABU + 268288)
#define O_WUC   (O_ABV + 268288)          // 1024*524
#define O_WVC   (O_WUC + 536576)
#define O_UBAR  (O_WVC + 536576)          // 512*1042
#define O_VBAR  (O_UBAR + 533504)
#define SCRATCH_TOTAL (O_VBAR + 533504)

__device__ float d_scratch[SCRATCH_TOTAL];
__device__ unsigned d_arrive;

__global__ void reset_kernel(float* hbuf) {
    int t = blockIdx.x * blockDim.x + threadIdx.x;
    if (t == 0) d_arrive = 0u;
    if (t < 2048) hbuf[t] = 0.f;   // parity-0 h states (both dirs) = zeros
}

__global__ void embed_kernel(const int* __restrict__ toks, const float* __restrict__ mask,
                             const float* __restrict__ gen, const float* __restrict__ dom,
                             float* __restrict__ emb) {
    int row = blockIdx.x;
    int tok = toks[row];
    float m = mask[row];
    for (int j = threadIdx.x; j < EMBD; j += blockDim.x) {
        float v = (j < 300) ? gen[tok * 300 + j] : dom[tok * 100 + (j - 300)];
        emb[row * EMBD + j] = v * m;
    }
}

// C[M,N] = A[M,K] @ Bw[N,K]^T + bias1 + bias2   (M,N multiples of 64)
__global__ __launch_bounds__(256)
void sgemm_abt(const float* __restrict__ A, int lda,
               const float* __restrict__ Bw, int ldb,
               const float* __restrict__ bias1, const float* __restrict__ bias2,
               float* __restrict__ Cout, int ldc, int K) {
    __shared__ float As[16][65];
    __shared__ float Bs[16][65];
    const int m0 = blockIdx.y * 64;
    const int n0 = blockIdx.x * 64;
    const int tid = threadIdx.x;
    const int tr = tid >> 4, tc = tid & 15;
    float acc[4][4];
#pragma unroll
    for (int i = 0; i < 4; i++)
#pragma unroll
        for (int j = 0; j < 4; j++) acc[i][j] = 0.f;

    for (int k0 = 0; k0 < K; k0 += 16) {
#pragma unroll
        for (int i = 0; i < 4; i++) {
            int e = tid + i * 256;
            int m = e >> 4, kk = e & 15;
            int kg = k0 + kk;
            float av = 0.f, bv = 0.f;
            if (kg < K) {
                av = A[(size_t)(m0 + m) * lda + kg];
                bv = Bw[(size_t)(n0 + m) * ldb + kg];
            }
            As[kk][m] = av;
            Bs[kk][m] = bv;
        }
        __syncthreads();
#pragma unroll
        for (int kk = 0; kk < 16; kk++) {
            float ra[4], rb[4];
#pragma unroll
            for (int i = 0; i < 4; i++) ra[i] = As[kk][tr * 4 + i];
#pragma unroll
            for (int j = 0; j < 4; j++) rb[j] = Bs[kk][tc * 4 + j];
#pragma unroll
            for (int i = 0; i < 4; i++)
#pragma unroll
                for (int j = 0; j < 4; j++) acc[i][j] = fmaf(ra[i], rb[j], acc[i][j]);
        }
        __syncthreads();
    }
#pragma unroll
    for (int j = 0; j < 4; j++) {
        int n = n0 + tc * 4 + j;
        float bb = 0.f;
        if (bias1) bb += bias1[n];
        if (bias2) bb += bias2[n];
#pragma unroll
        for (int i = 0; i < 4; i++)
            Cout[(size_t)(m0 + tr * 4 + i) * ldc + n] = acc[i][j] + bb;
    }
}

// BiLSTM: 128 co-resident blocks, each owns 4 hidden dims of one direction.
__global__ __launch_bounds__(256)
void lstm_kernel(const float* __restrict__ whh_f, const float* __restrict__ whh_b,
                 const float* __restrict__ pre,   // [2][BL][1024]
                 float* __restrict__ hglob,       // [2 parity][2 dir][4 batch][256]
                 float* __restrict__ ctx)         // [BL][512]
{
    const int blk = blockIdx.x;
    const int dir = blk >> 6;
    const int D0 = (blk & 63) * 4;
    const float* __restrict__ whh = dir ? whh_b : whh_f;
    const int tid = threadIdx.x;
    const int dotIdx = tid >> 2;      // 0..63: batch*16 + (gate*4+dim)
    const int quarter = tid & 3;
    const int r = dotIdx & 15;
    const int batch = dotIdx >> 4;
    const int gate = r >> 2, dim = r & 3;
    const int rowG = gate * 256 + D0 + dim;

    float4 w[16];
    {
        const float4* wp = reinterpret_cast<const float4*>(whh + (size_t)rowG * 256 + quarter * 64);
#pragma unroll
        for (int i = 0; i < 16; i++) w[i] = wp[i];
    }

    __shared__ float hsh[4][256];
    __shared__ float gsh[64];
    float cst = 0.f;
    const int sd = tid >> 2, sb = tid & 3;

    for (int step = 0; step < Ln; step++) {
        const int p = step & 1;
        {
            int hb = tid >> 6, k4 = tid & 63;
            const float4* src = reinterpret_cast<const float4*>(hglob + ((size_t)(p * 2 + dir) * 4 + hb) * 256) + k4;
            float4 v = __ldcg(src);
            reinterpret_cast<float4*>(&hsh[hb][0])[k4] = v;
        }
        __syncthreads();

        float acc = 0.f;
        {
            const float4* hp = reinterpret_cast<const float4*>(&hsh[batch][quarter * 64]);
#pragma unroll
            for (int i = 0; i < 16; i++) {
                float4 hv = hp[i];
                acc = fmaf(w[i].x, hv.x, acc);
                acc = fmaf(w[i].y, hv.y, acc);
                acc = fmaf(w[i].z, hv.z, acc);
                acc = fmaf(w[i].w, hv.w, acc);
            }
        }
        acc += __shfl_xor_sync(0xffffffffu, acc, 1);
        acc += __shfl_xor_sync(0xffffffffu, acc, 2);

        const int time = dir ? (127 - step) : step;
        if (quarter == 0)
            gsh[dotIdx] = acc + pre[((size_t)dir * BL + (batch << 7) + time) * 1024 + rowG];
        __syncthreads();

        if (tid < 16) {
            float gi = gsh[sb * 16 + sd];
            float gf = gsh[sb * 16 + 4 + sd];
            float gg = gsh[sb * 16 + 8 + sd];
            float go = gsh[sb * 16 + 12 + sd];
            float ii = 1.f / (1.f + expf(-gi));
            float ff = 1.f / (1.f + expf(-gf));
            float oo = 1.f / (1.f + expf(-go));
            float gt = tanhf(gg);
            cst = ff * cst + ii * gt;
            float hv = oo * tanhf(cst);
            __stcg(hglob + ((size_t)((p ^ 1) * 2 + dir) * 4 + sb) * 256 + D0 + sd, hv);
            ctx[((size_t)(sb << 7) + time) * 512 + dir * 256 + D0 + sd] = hv;
            __threadfence();
        }
        __syncthreads();
        if (tid == 0) {
            atomicAdd(&d_arrive, 1u);
            unsigned target = (unsigned)(step + 1) * (unsigned)LSTM_BLOCKS;
            volatile unsigned* va = &d_arrive;
            while (*va < target) { }
            __threadfence();
        }
        __syncthreads();
    }
}

// self-attention + residual, one block per (b,i) row
__global__ __launch_bounds__(256)
void attn_kernel(const float* __restrict__ q, const float* __restrict__ k,
                 const float* __restrict__ ctx, float* __restrict__ ctx2) {
    int row = blockIdx.x;
    int b = row >> 7;
    int tid = threadIdx.x;
    __shared__ float qsh[512];
    __shared__ float sc[128];
    __shared__ float red[128];
    for (int j = tid; j < 512; j += 256) qsh[j] = q[(size_t)row * 512 + j];
    __syncthreads();
    {
        int m = tid >> 1, half = tid & 1;
        const float* kr = k + ((size_t)(b * 128 + m)) * 512 + half * 256;
        const float* qh = qsh + half * 256;
        float s = 0.f;
#pragma unroll 8
        for (int j = 0; j < 256; j++) s = fmaf(qh[j], kr[j], s);
        s += __shfl_xor_sync(0xffffffffu, s, 1);
        if (!half) sc[m] = s;
    }
    __syncthreads();
    if (tid < 128) red[tid] = sc[tid];
    __syncthreads();
    for (int s = 64; s > 0; s >>= 1) {
        if (tid < s) red[tid] = fmaxf(red[tid], red[tid + s]);
        __syncthreads();
    }
    float mx = red[0];
    __syncthreads();
    if (tid < 128) { float e = expf(sc[tid] - mx); sc[tid] = e; red[tid] = e; }
    __syncthreads();
    for (int s = 64; s > 0; s >>= 1) {
        if (tid < s) red[tid] += red[tid + s];
        __syncthreads();
    }
    float inv = 1.f / red[0];
    __syncthreads();
    int c0 = tid * 2;
    float o0 = 0.f, o1 = 0.f;
    for (int m = 0; m < 128; m++) {
        float a = sc[m] * inv;
        float2 cv = *reinterpret_cast<const float2*>(ctx + ((size_t)(b * 128 + m)) * 512 + c0);
        o0 = fmaf(a, cv.x, o0);
        o1 = fmaf(a, cv.y, o1);
    }
    float2 base = *reinterpret_cast<const float2*>(ctx + (size_t)row * 512 + c0);
    float2 o; o.x = o0 + base.x; o.y = o1 + base.y;
    *reinterpret_cast<float2*>(ctx2 + (size_t)row * 512 + c0) = o;
}

// Cout[row][0..5] = A[row, :K] . W[c, off:off+K] + bias
__global__ __launch_bounds__(256)
void smallmm(const float* __restrict__ A, int lda, int K,
             const float* __restrict__ W, int ldw, int off,
             const float* __restrict__ bias, float* __restrict__ Cout) {
    int row = blockIdx.x;
    int tid = threadIdx.x;
    float acc[Cn] = {0, 0, 0, 0, 0, 0};
    const float* a = A + (size_t)row * lda;
    for (int kk = tid; kk < K; kk += 256) {
        float av = a[kk];
#pragma unroll
        for (int c = 0; c < Cn; c++) acc[c] = fmaf(av, W[(size_t)c * ldw + off + kk], acc[c]);
    }
    __shared__ float red[Cn][256];
#pragma unroll
    for (int c = 0; c < Cn; c++) red[c][tid] = acc[c];
    __syncthreads();
    for (int s = 128; s > 0; s >>= 1) {
        if (tid < s)
#pragma unroll
            for (int c = 0; c < Cn; c++) red[c][tid] += red[c][tid + s];
        __syncthreads();
    }
    if (tid < Cn) Cout[(size_t)row * Cn + tid] = red[tid][0] + (bias ? bias[tid] : 0.f);
}

// lm via prefix/suffix masked maxes (triu mask, full lengths)
__global__ void lm_kernel(const float* __restrict__ F, const float* __restrict__ G,
                          float* __restrict__ LM) {
    int t = threadIdx.x;
    if (t >= Bn * Cn) return;
    int b = t / Cn, c = t % Cn;
    const float* Fb = F + (size_t)(b * Ln) * Cn + c;
    const float* Gb = G + (size_t)(b * Ln) * Cn + c;
    float* Lb = LM + (size_t)(b * Ln) * Cn + c;
    float pf = -3.0e38f;
    for (int l = 0; l < Ln; l++) {
        pf = fmaxf(pf, Fb[l * Cn]);
        float v = Gb[l * Cn] + pf;
        if (l < Ln - 1) v = fmaxf(v, 0.f);
        Lb[l * Cn] = v;
    }
    float sg = -3.0e38f;
    for (int l = Ln - 1; l >= 0; l--) {
        sg = fmaxf(sg, Gb[l * Cn]);
        float v = Fb[l * Cn] + sg;
        if (l > 0) v = fmaxf(v, 0.f);
        Lb[l * Cn] = fmaxf(Lb[l * Cn], v);
    }
}

// compact feat_w column-gather for hop 1 (U0/V0 zero halves removed)
__global__ void gather_w(const float* __restrict__ feat_w,
                         float* __restrict__ wUc, float* __restrict__ wVc) {
    int idx = blockIdx.x * blockDim.x + threadIdx.x;
    if (idx >= 1024 * KC1) return;
    int n = idx / KC1, j = idx % KC1;
    int srcU = (j < 512) ? j : ((j < 518) ? 1024 + (j - 512) : 1036 + (j - 518));
    int srcV = (j < 512) ? 512 + j : ((j < 518) ? 1030 + (j - 512) : 1036 + (j - 518));
    wUc[idx] = feat_w[(size_t)n * KFULL + srcU];
    wVc[idx] = feat_w[(size_t)n * KFULL + srcV];
}

__global__ void build_ab1(const float* __restrict__ ctx2, const float* __restrict__ LM,
                          const float* __restrict__ F, const float* __restrict__ G,
                          float* __restrict__ AbU, float* __restrict__ AbV) {
    int row = blockIdx.x;
    for (int j = threadIdx.x; j < KC1; j += blockDim.x) {
        float u, v;
        if (j < 512) { u = v = ctx2[(size_t)row * 512 + j]; }
        else if (j < 518) { u = v = LM[(size_t)row * Cn + (j - 512)]; }
        else { u = F[(size_t)row * Cn + (j - 518)]; v = G[(size_t)row * Cn + (j - 518)]; }
        AbU[(size_t)row * KC1 + j] = u;
        AbV[(size_t)row * KC1 + j] = v;
    }
}

__global__ void build_bar(const float* __restrict__ U, const float* __restrict__ V,
                          const float* __restrict__ LM,
                          const float* __restrict__ F, const float* __restrict__ G,
                          float* __restrict__ Ub, float* __restrict__ Vb) {
    int row = blockIdx.x;
    for (int j = threadIdx.x; j < KFULL; j += blockDim.x) {
        float u, v;
        if (j < 1024) { u = U[(size_t)row * 1024 + j]; v = V[(size_t)row * 1024 + j]; }
        else if (j < 1030) { u = LM[(size_t)row * Cn + (j - 1024)]; v = 0.f; }
        else if (j < 1036) { u = 0.f; v = LM[(size_t)row * Cn + (j - 1030)]; }
        else { u = F[(size_t)row * Cn + (j - 1036)]; v = G[(size_t)row * Cn + (j - 1036)]; }
        Ub[(size_t)row * KFULL + j] = u;
        Vb[(size_t)row * KFULL + j] = v;
    }
}

__global__ void final_kernel(const float* __restrict__ F, const float* __restrict__ G,
                             float* __restrict__ out) {
    int idx = blockIdx.x * blockDim.x + threadIdx.x;
    if (idx >= Bn * Ln * Ln * Cn) return;
    int c = idx % Cn;
    int j = (idx / Cn) % Ln;
    int i = (idx / (Cn * Ln)) % Ln;
    int b = idx / (Cn * Ln * Ln);
    out[idx] = F[((size_t)(b * Ln + i)) * Cn + c] + G[((size_t)(b * Ln + j)) * Cn + c];
}

extern "C" void kernel_launch(void* const* d_in, const int* in_sizes, int n_in,
                              void* d_out, int out_size) {
    (void)in_sizes; (void)n_in; (void)out_size;
    const int*   toks   = (const int*)  d_in[0];
    const float* mask   = (const float*)d_in[2];
    const float* gen    = (const float*)d_in[3];
    const float* dom    = (const float*)d_in[4];
    const float* wih_f  = (const float*)d_in[5];
    const float* whh_f  = (const float*)d_in[6];
    const float* bih_f  = (const float*)d_in[7];
    const float* bhh_f  = (const float*)d_in[8];
    const float* wih_b  = (const float*)d_in[9];
    const float* whh_b  = (const float*)d_in[10];
    const float* bih_b  = (const float*)d_in[11];
    const float* bhh_b  = (const float*)d_in[12];
    const float* wq     = (const float*)d_in[13];
    const float* bq     = (const float*)d_in[14];
    const float* wk     = (const float*)d_in[15];
    const float* bk     = (const float*)d_in[16];
    const float* feat_w = (const float*)d_in[17];
    const float* feat_b = (const float*)d_in[18];
    const float* cls_w  = (const float*)d_in[19];
    const float* cls_b  = (const float*)d_in[20];
    float* out = (float*)d_out;

    float* S = nullptr;
    cudaGetSymbolAddress((void**)&S, d_scratch);
    float* emb  = S + O_EMB;
    float* pre  = S + O_PRE;
    float* hbuf = S + O_H;
    float* ctx  = S + O_CTX;
    float* qb   = S + O_Q;
    float* kb   = S + O_K;
    float* ctx2 = S + O_CTX2;
    float* F    = S + O_F;
    float* G    = S + O_G;
    float* LM   = S + O_LM;
    float* F2   = S + O_F2;
    float* G2   = S + O_G2;
    float* U    = S + O_U;
    float* V    = S + O_V;
    float* U2   = S + O_U2;
    float* V2   = S + O_V2;
    float* AbU  = S + O_ABU;
    float* AbV  = S + O_ABV;
    float* wUc  = S + O_WUC;
    float* wVc  = S + O_WVC;
    float* Ubar = S + O_UBAR;
    float* Vbar = S + O_VBAR;

    reset_kernel<<<8, 256>>>(hbuf);
    embed_kernel<<<BL, 128>>>(toks, mask, gen, dom, emb);

    // pre-activations: emb @ wih^T + bih + bhh, both directions
    dim3 gp(16, 8);
    sgemm_abt<<<gp, 256>>>(emb, EMBD, wih_f, EMBD, bih_f, bhh_f, pre, 1024, EMBD);
    sgemm_abt<<<gp, 256>>>(emb, EMBD, wih_b, EMBD, bih_b, bhh_b, pre + (size_t)BL * 1024, 1024, EMBD);

    lstm_kernel<<<LSTM_BLOCKS, 256>>>(whh_f, whh_b, pre, hbuf, ctx);

    dim3 gq(8, 8);
    sgemm_abt<<<gq, 256>>>(ctx, 512, wq, 512, bq, nullptr, qb, 512, 512);
    sgemm_abt<<<gq, 256>>>(ctx, 512, wk, 512, bk, nullptr, kb, 512, 512);
    attn_kernel<<<BL, 256>>>(qb, kb, ctx, ctx2);

    // logits0 split: F0 = ctx2 @ cls_w[:, :512]^T + cls_b ; G0 = ctx2 @ cls_w[:, 512:]^T
    smallmm<<<BL, 256>>>(ctx2, 512, 512, cls_w, 1024, 0, cls_b, F);
    smallmm<<<BL, 256>>>(ctx2, 512, 512, cls_w, 1024, 512, nullptr, G);

    gather_w<<<(1024 * KC1 + 255) / 256, 256>>>(feat_w, wUc, wVc);

    // ---- hop 1 (compact K=524) ----
    lm_kernel<<<1, 32>>>(F, G, LM);
    build_ab1<<<BL, 256>>>(ctx2, LM, F, G, AbU, AbV);
    sgemm_abt<<<gp, 256>>>(AbU, KC1, wUc, KC1, feat_b, nullptr, U, 1024, KC1);
    sgemm_abt<<<gp, 256>>>(AbV, KC1, wVc, KC1, nullptr, nullptr, V, 1024, KC1);
    smallmm<<<BL, 256>>>(U, 1024, 1024, cls_w, 1024, 0, cls_b, F2);
    smallmm<<<BL, 256>>>(V, 1024, 1024, cls_w, 1024, 0, nullptr, G2);

    // ---- hop 2 (full K=1042) ----
    lm_kernel<<<1, 32>>>(F2, G2, LM);
    build_bar<<<BL, 256>>>(U, V, LM, F2, G2, Ubar, Vbar);
    sgemm_abt<<<gp, 256>>>(Ubar, KFULL, feat_w, KFULL, feat_b, nullptr, U2, 1024, KFULL);
    sgemm_abt<<<gp, 256>>>(Vbar, KFULL, feat_w, KFULL, nullptr, nullptr, V2, 1024, KFULL);
    smallmm<<<BL, 256>>>(U2, 1024, 1024, cls_w, 1024, 0, cls_b, F);
    smallmm<<<BL, 256>>>(V2, 1024, 1024, cls_w, 1024, 0, nullptr, G);

    final_kernel<<<1536, 256>>>(F, G, out);
}

// round 3
// speedup vs baseline: 1.8447x; 1.8447x over previous
#include <cuda_runtime.h>
#include <math.h>
#include <stdint.h>

#define Bn 4
#define Ln 128
#define Cn 6
#define EMBD 400
#define BL 512
#define KC1P 528           // padded hop-1 K (524 -> 528)
#define KFP 1048           // padded hop-2 K (1042 -> 1048)
#define KFULL 1042

// ---------------- scratch layout (floats) ----------------
#define O_EMB   0
#define O_PRE   (O_EMB + 204800)           // 2*512*1024
#define O_CTX   (O_PRE + 1048576)          // 512*512
#define O_Q     (O_CTX + 262144)
#define O_K     (O_Q + 262144)
#define O_CTX2  (O_K + 262144)
#define O_F     (O_CTX2 + 262144)          // 512*6
#define O_G     (O_F + 3072)
#define O_LM    (O_G + 3072)
#define O_F2    (O_LM + 3072)
#define O_G2    (O_F2 + 3072)
#define O_U     (O_G2 + 3072)              // 512*1024
#define O_V     (O_U + 524288)
#define O_U2    (O_V + 524288)
#define O_V2    (O_U2 + 524288)
#define O_ABU   (O_V2 + 524288)            // 512*528
#define O_ABV   (O_ABU + 270336)
#define O_WUC   (O_ABV + 270336)           // 1024*528
#define O_WVC   (O_WUC + 540672)
#define O_WPAD  (O_WVC + 540672)           // 1024*1048
#define O_UBAR  (O_WPAD + 1073152)         // 512*1048
#define O_VBAR  (O_UBAR + 536576)
#define SCRATCH_TOTAL (O_VBAR + 536576)

__device__ float d_scratch[SCRATCH_TOTAL];

// ---------------- embedding gather ----------------
__global__ void embed_kernel(const int* __restrict__ toks, const float* __restrict__ mask,
                             const float* __restrict__ gen, const float* __restrict__ dom,
                             float* __restrict__ emb) {
    int row = blockIdx.x;
    int tok = toks[row];
    float m = mask[row];
    for (int j = threadIdx.x; j < EMBD; j += blockDim.x) {
        float v = (j < 300) ? gen[tok * 300 + j] : dom[tok * 100 + (j - 300)];
        emb[row * EMBD + j] = v * m;
    }
}

// ---------------- z-batched SGEMM: C[M,N] = A[M,K] @ W[N,K]^T + bx + by ----------------
// BM=BN=64, BK=8, 4x4 microtile, double-buffered smem, float4 everywhere.
// Requires K % 8 == 0, lda/ldw/ldc % 4 == 0, M,N multiples of 64.
__global__ __launch_bounds__(256, 2)
void sgemm2(const float* __restrict__ A0, const float* __restrict__ A1, int lda,
            const float* __restrict__ W0, const float* __restrict__ W1, int ldw,
            const float* __restrict__ bx0, const float* __restrict__ by0,
            const float* __restrict__ bx1, const float* __restrict__ by1,
            float* __restrict__ C0, float* __restrict__ C1, int ldc, int K)
{
    __shared__ float sm[2][2][8][68];   // [buf][side][kk][m-or-n]
    const int z = blockIdx.z;
    const float* A = z ? A1 : A0;
    const float* W = z ? W1 : W0;
    const float* bx = z ? bx1 : bx0;
    const float* by = z ? by1 : by0;
    float* C = z ? C1 : C0;
    const int m0 = blockIdx.y * 64, n0 = blockIdx.x * 64;
    const int tid = threadIdx.x;
    const int side = tid >> 7;          // 0 -> A tile, 1 -> W tile
    const int lrow = (tid & 127) >> 1;  // 0..63
    const int lq = tid & 1;             // which half of the 8-wide k slab
    const float* g = side ? (W + (size_t)(n0 + lrow) * ldw + lq * 4)
                          : (A + (size_t)(m0 + lrow) * lda + lq * 4);
    const int tr = tid >> 4, tc = tid & 15;

    float acc[4][4];
#pragma unroll
    for (int i = 0; i < 4; i++)
#pragma unroll
        for (int j = 0; j < 4; j++) acc[i][j] = 0.f;

    const int T = K >> 3;
    float4 v = *(const float4*)g;
    {
        float* sb = &sm[0][side][0][0];
        sb[(lq * 4 + 0) * 68 + lrow] = v.x;
        sb[(lq * 4 + 1) * 68 + lrow] = v.y;
        sb[(lq * 4 + 2) * 68 + lrow] = v.z;
        sb[(lq * 4 + 3) * 68 + lrow] = v.w;
    }
    __syncthreads();

    for (int t = 0; t < T; t++) {
        if (t + 1 < T) v = *(const float4*)(g + (size_t)(t + 1) * 8);
        const float* As = &sm[t & 1][0][0][0];
        const float* Bs = &sm[t & 1][1][0][0];
#pragma unroll
        for (int kk = 0; kk < 8; kk++) {
            float4 ra = *(const float4*)(As + kk * 68 + tr * 4);
            float4 rb = *(const float4*)(Bs + kk * 68 + tc * 4);
            acc[0][0] = fmaf(ra.x, rb.x, acc[0][0]);
            acc[0][1] = fmaf(ra.x, rb.y, acc[0][1]);
            acc[0][2] = fmaf(ra.x, rb.z, acc[0][2]);
            acc[0][3] = fmaf(ra.x, rb.w, acc[0][3]);
            acc[1][0] = fmaf(ra.y, rb.x, acc[1][0]);
            acc[1][1] = fmaf(ra.y, rb.y, acc[1][1]);
            acc[1][2] = fmaf(ra.y, rb.z, acc[1][2]);
            acc[1][3] = fmaf(ra.y, rb.w, acc[1][3]);
            acc[2][0] = fmaf(ra.z, rb.x, acc[2][0]);
            acc[2][1] = fmaf(ra.z, rb.y, acc[2][1]);
            acc[2][2] = fmaf(ra.z, rb.z, acc[2][2]);
            acc[2][3] = fmaf(ra.z, rb.w, acc[2][3]);
            acc[3][0] = fmaf(ra.w, rb.x, acc[3][0]);
            acc[3][1] = fmaf(ra.w, rb.y, acc[3][1]);
            acc[3][2] = fmaf(ra.w, rb.z, acc[3][2]);
            acc[3][3] = fmaf(ra.w, rb.w, acc[3][3]);
        }
        if (t + 1 < T) {
            float* sb = &sm[(t + 1) & 1][side][0][0];
            sb[(lq * 4 + 0) * 68 + lrow] = v.x;
            sb[(lq * 4 + 1) * 68 + lrow] = v.y;
            sb[(lq * 4 + 2) * 68 + lrow] = v.z;
            sb[(lq * 4 + 3) * 68 + lrow] = v.w;
        }
        __syncthreads();
    }

    float bb[4];
#pragma unroll
    for (int j = 0; j < 4; j++) {
        int n = n0 + tc * 4 + j;
        float b = 0.f;
        if (bx) b += bx[n];
        if (by) b += by[n];
        bb[j] = b;
    }
#pragma unroll
    for (int i = 0; i < 4; i++) {
        float4 o;
        o.x = acc[i][0] + bb[0];
        o.y = acc[i][1] + bb[1];
        o.z = acc[i][2] + bb[2];
        o.w = acc[i][3] + bb[3];
        *(float4*)(C + (size_t)(m0 + tr * 4 + i) * ldc + n0 + tc * 4) = o;
    }
}

// ---------------- BiLSTM via 8-CTA clusters (one cluster per dir x batch) ----------------
__global__ __launch_bounds__(256, 1) __cluster_dims__(8, 1, 1)
void lstm_cluster(const float* __restrict__ whh_f, const float* __restrict__ whh_b,
                  const float* __restrict__ pre,   // [2][512][1024]
                  float* __restrict__ ctx)         // [512][512]
{
    __shared__ float hb[2][264];     // h double buffer; second half at +132 (bank pad)
    const int tid = threadIdx.x;
    unsigned rank;
    asm("mov.u32 %0, %%cluster_ctarank;" : "=r"(rank));
    const int cid = blockIdx.x >> 3;
    const int dir = cid >> 2;
    const int batch = cid & 3;
    const int ct = (int)rank * 256 + tid;   // 0..2047 cluster thread id
    const int half = ct & 1;
    const int p = ct >> 1;                  // 0..1023 gate-row pair
    const int gate = p & 3;                 // i,f,g,o
    const int d = p >> 2;                   // hidden dim 0..255
    const int lane = tid & 31;
    const int gbase = lane & ~7;
    const bool prod = (ct & 7) == 0;        // owner of dim d: computes c,h
    const int dslot = (d < 128) ? d : d + 4;

    const float* whh = dir ? whh_b : whh_f;
    float4 w[32];
    {
        const float4* wp = (const float4*)(whh + ((size_t)(gate * 256 + d)) * 256 + half * 128);
#pragma unroll
        for (int i = 0; i < 32; i++) w[i] = wp[i];
    }
    for (int j = tid; j < 264; j += 256) hb[0][j] = 0.f;

    const float* preB = pre + ((size_t)dir * 512 + batch * 128) * 1024 + gate * 256 + d;
    float* ctxB = ctx + ((size_t)batch * 128) * 512 + dir * 256 + d;

    uint32_t la0 = (uint32_t)__cvta_generic_to_shared(&hb[0][dslot]);
    uint32_t la1 = (uint32_t)__cvta_generic_to_shared(&hb[1][dslot]);

    asm volatile("barrier.cluster.arrive.aligned;" ::: "memory");
    float preCur = preB[(size_t)(dir ? 127 : 0) * 1024];
    float cc = 0.f;

    for (int s = 0; s < 128; s++) {
        asm volatile("barrier.cluster.wait.aligned;" ::: "memory");
        const float4* hp = (const float4*)(&hb[s & 1][half ? 132 : 0]);
        float acc = 0.f;
#pragma unroll
        for (int i = 0; i < 32; i++) {
            float4 hv = hp[i];
            acc = fmaf(w[i].x, hv.x, acc);
            acc = fmaf(w[i].y, hv.y, acc);
            acc = fmaf(w[i].z, hv.z, acc);
            acc = fmaf(w[i].w, hv.w, acc);
        }
        acc += __shfl_xor_sync(0xffffffffu, acc, 1);
        float gv = acc + preCur;
        float gi = __shfl_sync(0xffffffffu, gv, gbase);
        float gf = __shfl_sync(0xffffffffu, gv, gbase + 2);
        float gg = __shfl_sync(0xffffffffu, gv, gbase + 4);
        float go = __shfl_sync(0xffffffffu, gv, gbase + 6);
        int time = dir ? (127 - s) : s;
        if (prod) {
            float ii = 1.f / (1.f + expf(-gi));
            float ff = 1.f / (1.f + expf(-gf));
            float oo = 1.f / (1.f + expf(-go));
            float gt = tanhf(gg);
            cc = ff * cc + ii * gt;
            float hv = oo * tanhf(cc);
            uint32_t la = ((s + 1) & 1) ? la1 : la0;
#pragma unroll
            for (int r = 0; r < 8; r++) {
                uint32_t ra;
                asm("mapa.shared::cluster.u32 %0, %1, %2;" : "=r"(ra) : "r"(la), "r"(r));
                asm volatile("st.shared::cluster.f32 [%0], %1;" :: "r"(ra), "f"(hv));
            }
            ctxB[(size_t)time * 512] = hv;
        }
        asm volatile("barrier.cluster.arrive.aligned;" ::: "memory");
        if (s < 127) {
            int tn = dir ? (126 - s) : (s + 1);
            preCur = preB[(size_t)tn * 1024];
        }
    }
    asm volatile("barrier.cluster.wait.aligned;" ::: "memory");
}

// ---------------- self-attention + residual ----------------
__global__ __launch_bounds__(256)
void attn_kernel(const float* __restrict__ q, const float* __restrict__ k,
                 const float* __restrict__ ctx, float* __restrict__ ctx2) {
    int row = blockIdx.x;
    int b = row >> 7;
    int tid = threadIdx.x;
    __shared__ float qsh[512];
    __shared__ float sc[128];
    __shared__ float red[128];
    for (int j = tid; j < 512; j += 256) qsh[j] = q[(size_t)row * 512 + j];
    __syncthreads();
    {
        int m = tid >> 1, half = tid & 1;
        const float* kr = k + ((size_t)(b * 128 + m)) * 512 + half * 256;
        const float* qh = qsh + half * 256;
        float s = 0.f;
#pragma unroll 8
        for (int j = 0; j < 256; j++) s = fmaf(qh[j], kr[j], s);
        s += __shfl_xor_sync(0xffffffffu, s, 1);
        if (!half) sc[m] = s;
    }
    __syncthreads();
    if (tid < 128) red[tid] = sc[tid];
    __syncthreads();
    for (int s = 64; s > 0; s >>= 1) {
        if (tid < s) red[tid] = fmaxf(red[tid], red[tid + s]);
        __syncthreads();
    }
    float mx = red[0];
    __syncthreads();
    if (tid < 128) { float e = expf(sc[tid] - mx); sc[tid] = e; red[tid] = e; }
    __syncthreads();
    for (int s = 64; s > 0; s >>= 1) {
        if (tid < s) red[tid] += red[tid + s];
        __syncthreads();
    }
    float inv = 1.f / red[0];
    __syncthreads();
    int c0 = tid * 2;
    float o0 = 0.f, o1 = 0.f;
    for (int m = 0; m < 128; m++) {
        float a = sc[m] * inv;
        float2 cv = *reinterpret_cast<const float2*>(ctx + ((size_t)(b * 128 + m)) * 512 + c0);
        o0 = fmaf(a, cv.x, o0);
        o1 = fmaf(a, cv.y, o1);
    }
    float2 base = *reinterpret_cast<const float2*>(ctx + (size_t)row * 512 + c0);
    float2 o; o.x = o0 + base.x; o.y = o1 + base.y;
    *reinterpret_cast<float2*>(ctx2 + (size_t)row * 512 + c0) = o;
}

// ---------------- z-paired thin matmul -> 6 classes per row ----------------
__global__ __launch_bounds__(256)
void smallmm2(const float* __restrict__ A0, const float* __restrict__ A1, int lda, int K,
              const float* __restrict__ W, int ldw, int off0, int off1,
              const float* __restrict__ bias, float* __restrict__ C0, float* __restrict__ C1) {
    int z = blockIdx.z;
    const float* A = (z ? A1 : A0) + (size_t)blockIdx.x * lda;
    int off = z ? off1 : off0;
    float* C = (z ? C1 : C0) + (size_t)blockIdx.x * Cn;
    int tid = threadIdx.x;
    float acc[Cn] = {0, 0, 0, 0, 0, 0};
    for (int k4 = tid; k4 * 4 < K; k4 += 256) {
        float4 a = *(const float4*)(A + k4 * 4);
#pragma unroll
        for (int c = 0; c < Cn; c++) {
            float4 wv = *(const float4*)(W + (size_t)c * ldw + off + k4 * 4);
            acc[c] += a.x * wv.x + a.y * wv.y + a.z * wv.z + a.w * wv.w;
        }
    }
    __shared__ float red[Cn][256];
#pragma unroll
    for (int c = 0; c < Cn; c++) red[c][tid] = acc[c];
    __syncthreads();
    for (int s = 128; s > 0; s >>= 1) {
        if (tid < s)
#pragma unroll
            for (int c = 0; c < Cn; c++) red[c][tid] += red[c][tid + s];
        __syncthreads();
    }
    if (tid < Cn) C[tid] = red[tid][0] + ((z == 0 && bias) ? bias[tid] : 0.f);
}

// ---------------- lm via prefix/suffix masked maxes ----------------
__global__ void lm_kernel(const float* __restrict__ F, const float* __restrict__ G,
                          float* __restrict__ LM) {
    int t = threadIdx.x;
    if (t >= Bn * Cn) return;
    int b = t / Cn, c = t % Cn;
    const float* Fb = F + (size_t)(b * Ln) * Cn + c;
    const float* Gb = G + (size_t)(b * Ln) * Cn + c;
    float* Lb = LM + (size_t)(b * Ln) * Cn + c;
    float pf = -3.0e38f;
    for (int l = 0; l < Ln; l++) {
        pf = fmaxf(pf, Fb[l * Cn]);
        float v = Gb[l * Cn] + pf;
        if (l < Ln - 1) v = fmaxf(v, 0.f);
        Lb[l * Cn] = v;
    }
    float sg = -3.0e38f;
    for (int l = Ln - 1; l >= 0; l--) {
        sg = fmaxf(sg, Gb[l * Cn]);
        float v = Fb[l * Cn] + sg;
        if (l > 0) v = fmaxf(v, 0.f);
        Lb[l * Cn] = fmaxf(Lb[l * Cn], v);
    }
}

// ---------------- feat_w gathers (compact hop-1 slices + padded full copy) ----------------
__global__ void gather_w(const float* __restrict__ feat_w,
                         float* __restrict__ wUc, float* __restrict__ wVc) {
    int idx = blockIdx.x * blockDim.x + threadIdx.x;
    if (idx >= 1024 * KC1P) return;
    int n = idx / KC1P, j = idx % KC1P;
    float u = 0.f, v = 0.f;
    if (j < 524) {
        int srcU = (j < 512) ? j : ((j < 518) ? 1024 + (j - 512) : 1036 + (j - 518));
        int srcV = (j < 512) ? 512 + j : ((j < 518) ? 1030 + (j - 512) : 1036 + (j - 518));
        u = feat_w[(size_t)n * KFULL + srcU];
        v = feat_w[(size_t)n * KFULL + srcV];
    }
    wUc[idx] = u;
    wVc[idx] = v;
}

__global__ void gather_wpad(const float* __restrict__ feat_w, float* __restrict__ wp) {
    int idx = blockIdx.x * blockDim.x + threadIdx.x;
    if (idx >= 1024 * KFP) return;
    int n = idx / KFP, j = idx % KFP;
    wp[idx] = (j < KFULL) ? feat_w[(size_t)n * KFULL + j] : 0.f;
}

__global__ void build_ab1(const float* __restrict__ ctx2, const float* __restrict__ LM,
                          const float* __restrict__ F, const float* __restrict__ G,
                          float* __restrict__ AbU, float* __restrict__ AbV) {
    int row = blockIdx.x;
    for (int j = threadIdx.x; j < KC1P; j += blockDim.x) {
        float u = 0.f, v = 0.f;
        if (j < 512) { u = v = ctx2[(size_t)row * 512 + j]; }
        else if (j < 518) { u = v = LM[(size_t)row * Cn + (j - 512)]; }
        else if (j < 524) { u = F[(size_t)row * Cn + (j - 518)]; v = G[(size_t)row * Cn + (j - 518)]; }
        AbU[(size_t)row * KC1P + j] = u;
        AbV[(size_t)row * KC1P + j] = v;
    }
}

__global__ void build_bar(const float* __restrict__ U, const float* __restrict__ V,
                          const float* __restrict__ LM,
                          const float* __restrict__ F, const float* __restrict__ G,
                          float* __restrict__ Ub, float* __restrict__ Vb) {
    int row = blockIdx.x;
    for (int j = threadIdx.x; j < KFP; j += blockDim.x) {
        float u = 0.f, v = 0.f;
        if (j < 1024) { u = U[(size_t)row * 1024 + j]; v = V[(size_t)row * 1024 + j]; }
        else if (j < 1030) { u = LM[(size_t)row * Cn + (j - 1024)]; v = 0.f; }
        else if (j < 1036) { u = 0.f; v = LM[(size_t)row * Cn + (j - 1030)]; }
        else if (j < 1042) { u = F[(size_t)row * Cn + (j - 1036)]; v = G[(size_t)row * Cn + (j - 1036)]; }
        Ub[(size_t)row * KFP + j] = u;
        Vb[(size_t)row * KFP + j] = v;
    }
}

__global__ void final_kernel(const float* __restrict__ F, const float* __restrict__ G,
                             float* __restrict__ out) {
    int idx = blockIdx.x * blockDim.x + threadIdx.x;
    if (idx >= Bn * Ln * Ln * Cn) return;
    int c = idx % Cn;
    int j = (idx / Cn) % Ln;
    int i = (idx / (Cn * Ln)) % Ln;
    int b = idx / (Cn * Ln * Ln);
    out[idx] = F[((size_t)(b * Ln + i)) * Cn + c] + G[((size_t)(b * Ln + j)) * Cn + c];
}

extern "C" void kernel_launch(void* const* d_in, const int* in_sizes, int n_in,
                              void* d_out, int out_size) {
    (void)in_sizes; (void)n_in; (void)out_size;
    const int*   toks   = (const int*)  d_in[0];
    const float* mask   = (const float*)d_in[2];
    const float* gen    = (const float*)d_in[3];
    const float* dom    = (const float*)d_in[4];
    const float* wih_f  = (const float*)d_in[5];
    const float* whh_f  = (const float*)d_in[6];
    const float* bih_f  = (const float*)d_in[7];
    const float* bhh_f  = (const float*)d_in[8];
    const float* wih_b  = (const float*)d_in[9];
    const float* whh_b  = (const float*)d_in[10];
    const float* bih_b  = (const float*)d_in[11];
    const float* bhh_b  = (const float*)d_in[12];
    const float* wq     = (const float*)d_in[13];
    const float* bq     = (const float*)d_in[14];
    const float* wk     = (const float*)d_in[15];
    const float* bk     = (const float*)d_in[16];
    const float* feat_w = (const float*)d_in[17];
    const float* feat_b = (const float*)d_in[18];
    const float* cls_w  = (const float*)d_in[19];
    const float* cls_b  = (const float*)d_in[20];
    float* out = (float*)d_out;

    float* S = nullptr;
    cudaGetSymbolAddress((void**)&S, d_scratch);
    float* emb  = S + O_EMB;
    float* pre  = S + O_PRE;
    float* ctx  = S + O_CTX;
    float* qb   = S + O_Q;
    float* kb   = S + O_K;
    float* ctx2 = S + O_CTX2;
    float* F    = S + O_F;
    float* G    = S + O_G;
    float* LM   = S + O_LM;
    float* F2   = S + O_F2;
    float* G2   = S + O_G2;
    float* U    = S + O_U;
    float* V    = S + O_V;
    float* U2   = S + O_U2;
    float* V2   = S + O_V2;
    float* AbU  = S + O_ABU;
    float* AbV  = S + O_ABV;
    float* wUc  = S + O_WUC;
    float* wVc  = S + O_WVC;
    float* Wpad = S + O_WPAD;
    float* Ubar = S + O_UBAR;
    float* Vbar = S + O_VBAR;

    embed_kernel<<<BL, 128>>>(toks, mask, gen, dom, emb);
    gather_w<<<(1024 * KC1P + 255) / 256, 256>>>(feat_w, wUc, wVc);
    gather_wpad<<<(1024 * KFP + 255) / 256, 256>>>(feat_w, Wpad);

    // pre-activations (both dirs in one launch): emb @ wih^T + bih + bhh
    sgemm2<<<dim3(16, 8, 2), 256>>>(emb, emb, EMBD, wih_f, wih_b, EMBD,
                                    bih_f, bhh_f, bih_b, bhh_b,
                                    pre, pre + (size_t)BL * 1024, 1024, EMBD);

    lstm_cluster<<<64, 256>>>(whh_f, whh_b, pre, ctx);

    // q/k projections in one launch
    sgemm2<<<dim3(8, 8, 2), 256>>>(ctx, ctx, 512, wq, wk, 512,
                                   bq, nullptr, bk, nullptr,
                                   qb, kb, 512, 512);
    attn_kernel<<<BL, 256>>>(qb, kb, ctx, ctx2);

    // F0 = ctx2 @ cls_w[:, :512]^T + cls_b ; G0 = ctx2 @ cls_w[:, 512:]^T
    smallmm2<<<dim3(BL, 1, 2), 256>>>(ctx2, ctx2, 512, 512, cls_w, 1024, 0, 512, cls_b, F, G);

    // ---- hop 1 (compact K=528) ----
    lm_kernel<<<1, 32>>>(F, G, LM);
    build_ab1<<<BL, 256>>>(ctx2, LM, F, G, AbU, AbV);
    sgemm2<<<dim3(16, 8, 2), 256>>>(AbU, AbV, KC1P, wUc, wVc, KC1P,
                                    feat_b, nullptr, nullptr, nullptr,
                                    U, V, 1024, KC1P);
    smallmm2<<<dim3(BL, 1, 2), 256>>>(U, V, 1024, 1024, cls_w, 1024, 0, 0, cls_b, F2, G2);

    // ---- hop 2 (padded K=1048) ----
    lm_kernel<<<1, 32>>>(F2, G2, LM);
    build_bar<<<BL, 256>>>(U, V, LM, F2, G2, Ubar, Vbar);
    sgemm2<<<dim3(16, 8, 2), 256>>>(Ubar, Vbar, KFP, Wpad, Wpad, KFP,
                                    feat_b, nullptr, nullptr, nullptr,
                                    U2, V2, 1024, KFP);
    smallmm2<<<dim3(BL, 1, 2), 256>>>(U2, V2, 1024, 1024, cls_w, 1024, 0, 0, cls_b, F, G);

    final_kernel<<<1536, 256>>>(F, G, out);
}